// round 6
// baseline (speedup 1.0000x reference)
#include <cuda_runtime.h>
#include <cuda_bf16.h>
#include <cstdint>
#include <cstddef>

// ---------------------------------------------------------------------------
// Problem constants
// ---------------------------------------------------------------------------
#define BB_ 4
#define TT_ 4096
#define DD_ 1024
#define MM_ (BB_ * TT_)   // 16384 rows
#define E3_ (3 * DD_)     // 3072

// ---------------------------------------------------------------------------
// Scratch (static device globals -- allocation-free rule)
// ---------------------------------------------------------------------------
__device__ float g_qkv[(size_t)MM_ * E3_];
__device__ signed char g_a_hi[(size_t)MM_ * DD_];     // x slices, reused for A2
__device__ signed char g_a_lo[(size_t)MM_ * DD_];
__device__ signed char g_wq_hi[(size_t)E3_ * DD_];
__device__ signed char g_wq_lo[(size_t)E3_ * DD_];
__device__ signed char g_wo_hi[(size_t)DD_ * DD_];
__device__ signed char g_wo_lo[(size_t)DD_ * DD_];
__device__ float g_sa[MM_];     // row scales for A (x, then A2)
__device__ float g_swq[E3_];
__device__ float g_swo[DD_];
__device__ float g_invq[MM_];
__device__ float g_kv[BB_ * DD_];
__device__ int   g_mask_is_byte;

#define SLICE_S 252.0f
#define INV_SLICE_S (1.0f / 252.0f)

// ---------------------------------------------------------------------------
// Helpers (sm_103 baseline ISA: cp.async, ldmatrix, mma.sync)
// ---------------------------------------------------------------------------
__device__ __forceinline__ uint32_t smem_to_u32(const void* smem_ptr) {
    uint32_t addr;
    asm("{ .reg .u64 tmp; cvta.to.shared.u64 tmp, %1; cvt.u32.u64 %0, tmp; }"
        : "=r"(addr) : "l"(smem_ptr));
    return addr;
}

__device__ __forceinline__ void cp16(uint32_t smem_dst, const void* gmem_src) {
    asm volatile("cp.async.cg.shared.global [%0], [%1], 16;\n"
                 :: "r"(smem_dst), "l"(gmem_src));
}
#define CP_ASYNC_COMMIT() asm volatile("cp.async.commit_group;\n" ::: "memory")
#define CP_ASYNC_WAIT_1() asm volatile("cp.async.wait_group 1;\n" ::: "memory")
#define CP_ASYNC_WAIT_0() asm volatile("cp.async.wait_group 0;\n" ::: "memory")

#define LDSM_X4(r0, r1, r2, r3, addr) \
    asm volatile("ldmatrix.sync.aligned.m8n8.x4.shared.b16 {%0,%1,%2,%3}, [%4];" \
                 : "=r"(r0), "=r"(r1), "=r"(r2), "=r"(r3) : "r"(addr))

// int8 MMA: D(s32) += A(s8 16x32) * B(s8 32x8)^T
#define IMMA_16832(c, a, b) \
    asm volatile("mma.sync.aligned.m16n8k32.row.col.s32.s8.s8.s32 " \
                 "{%0,%1,%2,%3}, {%4,%5,%6,%7}, {%8,%9}, {%0,%1,%2,%3};" \
                 : "+r"((c)[0]), "+r"((c)[1]), "+r"((c)[2]), "+r"((c)[3]) \
                 : "r"((a)[0]), "r"((a)[1]), "r"((a)[2]), "r"((a)[3]), \
                   "r"((b)[0]), "r"((b)[1]))

#define SMEM_SWIZZLE_128B(byte_offset) \
    ((byte_offset) ^ (((byte_offset) >> 3) & 0x70))

// ---------------------------------------------------------------------------
// int8 GEMM: C[m,n] = sA[m]*sB[n]*( Ah.Bh + (Ah.Bl + Al.Bh)/252 ) + bias[n]
// A: (M,1024) int8 row-major slices; B: (N,1024) int8 row-major slices.
// CTA tile 128x128, BK=128 bytes; 512 thr = 16 warps 4(M)x4(N), warp 32x32.
// Stage: [Ah 16K][Al 16K][Bh 16K][Bl 16K] = 64KB; 3-stage cp.async ring.
// ---------------------------------------------------------------------------
#define STAGES 3
#define STAGE_BYTES 65536
#define GS_TOTAL (STAGES * STAGE_BYTES)   // 196608
#define NKT8 8        // 1024 / 128
#define NTHR 512

__device__ __forceinline__ void gemm_issue_load_i8(
    uint32_t sb, int slot, int tid, int m0, int n0, int kt,
    const signed char* __restrict__ Ah, const signed char* __restrict__ Al,
    const signed char* __restrict__ Bh, const signed char* __restrict__ Bl)
{
    uint32_t base = sb + slot * STAGE_BYTES;
    int k0 = kt << 7;   // byte offset within 1024-byte row
    const signed char* srcs[4] = { Ah, Al, Bh, Bl };
    #pragma unroll
    for (int i = 0; i < 8; i++) {
        const int part = i >> 1;                  // compile-time
        int cid = tid + ((i & 1) << 9);           // 0..1023
        int r  = cid >> 3;                        // row 0..127
        int cc = cid & 7;                         // 16B chunk
        int row0 = (part < 2) ? m0 : n0;
        uint32_t soff = SMEM_SWIZZLE_128B((uint32_t)((r << 7) + (cc << 4)));
        cp16(base + (part << 14) + soff,
             srcs[part] + (size_t)(row0 + r) * DD_ + k0 + (cc << 4));
    }
    CP_ASYNC_COMMIT();
}

__global__ __launch_bounds__(NTHR, 1) void gemm_i8_kernel(
    const signed char* __restrict__ Ah, const signed char* __restrict__ Al,
    const float* __restrict__ sA,
    const signed char* __restrict__ Bh, const signed char* __restrict__ Bl,
    const float* __restrict__ sB,
    const float* __restrict__ bias, float* __restrict__ C, int N)
{
    extern __shared__ char smem[];
    uint32_t sb = smem_to_u32(smem);
    const int tid = threadIdx.x;
    const int wid = tid >> 5;
    const int lane = tid & 31;
    const int n0 = blockIdx.x * 128;
    const int m0 = blockIdx.y * 128;
    const int warp_m = (wid & 3) * 32;
    const int warp_n = (wid >> 2) * 32;

    // ldmatrix per-lane components (byte layout identical to bf16 case)
    const int lr = lane & 7;
    const int a_row = warp_m + lr + ((lane & 8) ? 8 : 0);
    const int a_ksel = (lane & 16) ? 16 : 0;
    const int b_row = warp_n + lr + ((lane & 16) ? 8 : 0);
    const int b_ksel = (lane & 8) ? 16 : 0;

    int hh[2][4][4];   // Ah.Bh accumulator
    int xx[2][4][4];   // Ah.Bl + Al.Bh accumulator
    #pragma unroll
    for (int i = 0; i < 2; i++)
        #pragma unroll
        for (int j = 0; j < 4; j++)
            #pragma unroll
            for (int k = 0; k < 4; k++) { hh[i][j][k] = 0; xx[i][j][k] = 0; }

    // prologue: stages 0,1
    gemm_issue_load_i8(sb, 0, tid, m0, n0, 0, Ah, Al, Bh, Bl);
    gemm_issue_load_i8(sb, 1, tid, m0, n0, 1, Ah, Al, Bh, Bl);

    int slot = 0;
    for (int it = 0; it < NKT8; it++) {
        if (it == NKT8 - 1) { CP_ASYNC_WAIT_0(); } else { CP_ASYNC_WAIT_1(); }
        __syncthreads();

        int nt = it + 2;
        if (nt < NKT8) {
            int ns = slot + 2; if (ns >= STAGES) ns -= STAGES;
            gemm_issue_load_i8(sb, ns, tid, m0, n0, nt, Ah, Al, Bh, Bl);
        }

        uint32_t ab_h = sb + slot * STAGE_BYTES;
        uint32_t ab_l = ab_h + 16384;
        uint32_t bb_h = ab_h + 32768;
        uint32_t bb_l = ab_h + 49152;

        #pragma unroll
        for (int ks = 0; ks < 4; ks++) {
            const int koff = ks << 5;   // 32 bytes per k-step
            // Bh fragments (4 n8 tiles)
            uint32_t bh[4][2];
            #pragma unroll
            for (int nb = 0; nb < 2; nb++) {
                int row = b_row + nb * 16;
                uint32_t addr = bb_h + (uint32_t)(row << 7)
                              + (uint32_t)((koff + b_ksel) ^ ((row & 7) << 4));
                LDSM_X4(bh[2 * nb][0], bh[2 * nb][1],
                        bh[2 * nb + 1][0], bh[2 * nb + 1][1], addr);
            }
            // Ah fragments (2 m16 tiles)
            uint32_t af[2][4];
            #pragma unroll
            for (int mf = 0; mf < 2; mf++) {
                int row = a_row + mf * 16;
                uint32_t addr = ab_h + (uint32_t)(row << 7)
                              + (uint32_t)((koff + a_ksel) ^ ((row & 7) << 4));
                LDSM_X4(af[mf][0], af[mf][1], af[mf][2], af[mf][3], addr);
            }
            // P1: Ah.Bh -> hh
            #pragma unroll
            for (int mf = 0; mf < 2; mf++)
                #pragma unroll
                for (int nf = 0; nf < 4; nf++)
                    IMMA_16832(hh[mf][nf], af[mf], bh[nf]);
            // Bl fragments
            uint32_t bl[4][2];
            #pragma unroll
            for (int nb = 0; nb < 2; nb++) {
                int row = b_row + nb * 16;
                uint32_t addr = bb_l + (uint32_t)(row << 7)
                              + (uint32_t)((koff + b_ksel) ^ ((row & 7) << 4));
                LDSM_X4(bl[2 * nb][0], bl[2 * nb][1],
                        bl[2 * nb + 1][0], bl[2 * nb + 1][1], addr);
            }
            // P2: Ah.Bl -> xx
            #pragma unroll
            for (int mf = 0; mf < 2; mf++)
                #pragma unroll
                for (int nf = 0; nf < 4; nf++)
                    IMMA_16832(xx[mf][nf], af[mf], bl[nf]);
            // Al fragments (reuse af regs)
            #pragma unroll
            for (int mf = 0; mf < 2; mf++) {
                int row = a_row + mf * 16;
                uint32_t addr = ab_l + (uint32_t)(row << 7)
                              + (uint32_t)((koff + a_ksel) ^ ((row & 7) << 4));
                LDSM_X4(af[mf][0], af[mf][1], af[mf][2], af[mf][3], addr);
            }
            // P3: Al.Bh -> xx
            #pragma unroll
            for (int mf = 0; mf < 2; mf++)
                #pragma unroll
                for (int nf = 0; nf < 4; nf++)
                    IMMA_16832(xx[mf][nf], af[mf], bh[nf]);
        }
        slot++; if (slot >= STAGES) slot = 0;
    }

    // epilogue: combine slices with scales + bias
    const int gid = lane >> 2;
    const int t4 = lane & 3;
    #pragma unroll
    for (int mf = 0; mf < 2; mf++) {
        int r0 = m0 + warp_m + mf * 16 + gid;
        float sa0 = sA[r0];
        float sa1 = sA[r0 + 8];
        #pragma unroll
        for (int nf = 0; nf < 4; nf++) {
            int c = n0 + warp_n + nf * 8 + t4 * 2;
            float sb0 = sB[c], sb1 = sB[c + 1];
            float bi0 = bias[c], bi1 = bias[c + 1];
            float p00 = (float)hh[mf][nf][0] + (float)xx[mf][nf][0] * INV_SLICE_S;
            float p01 = (float)hh[mf][nf][1] + (float)xx[mf][nf][1] * INV_SLICE_S;
            float p10 = (float)hh[mf][nf][2] + (float)xx[mf][nf][2] * INV_SLICE_S;
            float p11 = (float)hh[mf][nf][3] + (float)xx[mf][nf][3] * INV_SLICE_S;
            float2 v0 = make_float2(sa0 * sb0 * p00 + bi0, sa0 * sb1 * p01 + bi1);
            float2 v1 = make_float2(sa1 * sb0 * p10 + bi0, sa1 * sb1 * p11 + bi1);
            *(float2*)(C + (size_t)r0 * N + c) = v0;
            *(float2*)(C + (size_t)(r0 + 8) * N + c) = v1;
        }
    }
}

// ---------------------------------------------------------------------------
// Quantization: fp32 rows -> int8 hi/lo slices + per-row scale
// ---------------------------------------------------------------------------
__device__ __forceinline__ float warp_max(float v) {
    #pragma unroll
    for (int o = 16; o > 0; o >>= 1)
        v = fmaxf(v, __shfl_xor_sync(0xffffffffu, v, o));
    return v;
}

__device__ __forceinline__ uint32_t pack4(int a0, int a1, int a2, int a3) {
    return (uint32_t)(a0 & 255) | ((uint32_t)(a1 & 255) << 8)
         | ((uint32_t)(a2 & 255) << 16) | ((uint32_t)(a3 & 255) << 24);
}

__device__ __forceinline__ void quant8(const float* v, float inv,
                                       uint32_t* p0, uint32_t* p1) {
    int ah[8], al[8];
    #pragma unroll
    for (int j = 0; j < 8; j++) {
        float t = v[j] * inv;
        float h = rintf(t);
        ah[j] = (int)h;
        al[j] = (int)rintf((t - h) * SLICE_S);
    }
    p0[0] = pack4(ah[0], ah[1], ah[2], ah[3]);
    p0[1] = pack4(ah[4], ah[5], ah[6], ah[7]);
    p1[0] = pack4(al[0], al[1], al[2], al[3]);
    p1[1] = pack4(al[4], al[5], al[6], al[7]);
}

// 2 rows per 256-thread block; each thread handles 8 consecutive elements.
__global__ __launch_bounds__(256) void quant_rows_kernel(
    const float* __restrict__ in, signed char* __restrict__ hi,
    signed char* __restrict__ lo, float* __restrict__ scale)
{
    __shared__ float s_max[8];
    int tid = threadIdx.x;
    int half = tid >> 7;                 // which row in block
    int tr = tid & 127;
    int row = blockIdx.x * 2 + half;
    const float* p = in + (size_t)row * DD_ + tr * 8;
    float v[8];
    *(float4*)(v)     = *(const float4*)(p);
    *(float4*)(v + 4) = *(const float4*)(p + 4);
    float m = 0.f;
    #pragma unroll
    for (int j = 0; j < 8; j++) m = fmaxf(m, fabsf(v[j]));
    m = warp_max(m);
    if ((tid & 31) == 0) s_max[tid >> 5] = m;
    __syncthreads();
    int wb = half * 4;
    float mrow = fmaxf(fmaxf(s_max[wb], s_max[wb + 1]),
                       fmaxf(s_max[wb + 2], s_max[wb + 3]));
    float inv = (mrow > 0.f) ? (127.0f / mrow) : 0.f;
    if (tr == 0) scale[row] = mrow * (1.0f / 127.0f);
    uint32_t ph[2], pl[2];
    quant8(v, inv, ph, pl);
    *(uint2*)(hi + (size_t)row * DD_ + tr * 8) = make_uint2(ph[0], ph[1]);
    *(uint2*)(lo + (size_t)row * DD_ + tr * 8) = make_uint2(pl[0], pl[1]);
}

// ---------------------------------------------------------------------------
// Elementwise / reduction kernels
// ---------------------------------------------------------------------------
__global__ void zero_kv_kernel(float* __restrict__ kv)
{
    int i = blockIdx.x * blockDim.x + threadIdx.x;
    if (i < BB_ * DD_) kv[i] = 0.0f;
}

__global__ void detect_mask_kernel(const unsigned char* __restrict__ m)
{
    __shared__ int any;
    if (threadIdx.x == 0) any = 0;
    __syncthreads();
    int acc = 0;
    for (int i = threadIdx.x; i < MM_; i += blockDim.x)
        if ((i & 3) != 0) acc |= m[i];
    if (acc) atomicOr(&any, 1);
    __syncthreads();
    if (threadIdx.x == 0) g_mask_is_byte = any ? 1 : 0;
}

__global__ __launch_bounds__(256) void stage2_kernel(
    const float* __restrict__ qkv, const unsigned char* __restrict__ mask,
    float* __restrict__ invq, float* __restrict__ kv)
{
    __shared__ float s_ik[32];
    int tid = threadIdx.x, lane = tid & 31, warp = tid >> 5;
    int R0 = blockIdx.x * 32;
    int b = R0 >> 12;
    int maskIsByte = g_mask_is_byte;
    const int* mask32 = (const int*)mask;

    #pragma unroll
    for (int rr = 0; rr < 4; rr++) {
        int row = R0 + warp * 4 + rr;
        const float4* base = (const float4*)(qkv + (size_t)row * E3_);
        float sq = 0.f, sk = 0.f;
        #pragma unroll
        for (int j = 0; j < 8; j++) {
            float4 q4 = base[lane + 32 * j];
            float4 k4 = base[256 + lane + 32 * j];
            sq += q4.x*q4.x + q4.y*q4.y + q4.z*q4.z + q4.w*q4.w;
            sk += k4.x*k4.x + k4.y*k4.y + k4.z*k4.z + k4.w*k4.w;
        }
        #pragma unroll
        for (int o = 16; o > 0; o >>= 1) {
            sq += __shfl_xor_sync(0xffffffffu, sq, o);
            sk += __shfl_xor_sync(0xffffffffu, sk, o);
        }
        if (lane == 0) {
            invq[row] = rsqrtf(sq);
            s_ik[warp * 4 + rr] = rsqrtf(sk);
        }
    }
    __syncthreads();

    float ax = 0.f, ay = 0.f, az = 0.f, aw = 0.f;
    for (int r = 0; r < 32; r++) {
        int row = R0 + r;
        bool msk = maskIsByte ? (mask[row] != 0) : (mask32[row] != 0);
        if (!msk) {
            float ik = s_ik[r];
            const float4* base = (const float4*)(qkv + (size_t)row * E3_);
            float4 k4 = base[256 + tid];
            float4 v4 = base[512 + tid];
            ax += k4.x * ik * v4.x;
            ay += k4.y * ik * v4.y;
            az += k4.z * ik * v4.z;
            aw += k4.w * ik * v4.w;
        }
    }
    float* kvb = kv + b * DD_ + tid * 4;
    atomicAdd(kvb + 0, ax);
    atomicAdd(kvb + 1, ay);
    atomicAdd(kvb + 2, az);
    atomicAdd(kvb + 3, aw);
}

// A2 = q * invq[row] * kv[b,:] -> int8 hi/lo slices + row scale.
// One block (128 threads) per row.
__global__ __launch_bounds__(128) void stage3_quant_kernel(
    const float* __restrict__ qkv, const float* __restrict__ invq,
    const float* __restrict__ kv,
    signed char* __restrict__ hi, signed char* __restrict__ lo,
    float* __restrict__ scale)
{
    __shared__ float s_max[4];
    int tid = threadIdx.x;
    int row = blockIdx.x;
    int b = row >> 12;
    float s = invq[row];
    const float* qp = qkv + (size_t)row * E3_ + tid * 8;
    const float* kp = kv + b * DD_ + tid * 8;
    float v[8];
    float4 q0 = *(const float4*)(qp);
    float4 q1 = *(const float4*)(qp + 4);
    float4 k0 = *(const float4*)(kp);
    float4 k1 = *(const float4*)(kp + 4);
    v[0] = q0.x * s * k0.x; v[1] = q0.y * s * k0.y;
    v[2] = q0.z * s * k0.z; v[3] = q0.w * s * k0.w;
    v[4] = q1.x * s * k1.x; v[5] = q1.y * s * k1.y;
    v[6] = q1.z * s * k1.z; v[7] = q1.w * s * k1.w;
    float m = 0.f;
    #pragma unroll
    for (int j = 0; j < 8; j++) m = fmaxf(m, fabsf(v[j]));
    m = warp_max(m);
    if ((tid & 31) == 0) s_max[tid >> 5] = m;
    __syncthreads();
    float mrow = fmaxf(fmaxf(s_max[0], s_max[1]), fmaxf(s_max[2], s_max[3]));
    float inv = (mrow > 0.f) ? (127.0f / mrow) : 0.f;
    if (tid == 0) scale[row] = mrow * (1.0f / 127.0f);
    uint32_t ph[2], pl[2];
    quant8(v, inv, ph, pl);
    *(uint2*)(hi + (size_t)row * DD_ + tid * 8) = make_uint2(ph[0], ph[1]);
    *(uint2*)(lo + (size_t)row * DD_ + tid * 8) = make_uint2(pl[0], pl[1]);
}

// ---------------------------------------------------------------------------
// Launch
// ---------------------------------------------------------------------------
extern "C" void kernel_launch(void* const* d_in, const int* in_sizes, int n_in,
                              void* d_out, int out_size)
{
    const float* x = (const float*)d_in[0];
    const unsigned char* mask = (const unsigned char*)d_in[1];
    const float* Wqkv = (const float*)d_in[2];
    const float* bqkv = (const float*)d_in[3];
    const float* Wout = (const float*)d_in[4];
    const float* bout = (const float*)d_in[5];
    float* out = (float*)d_out;

    float *p_qkv, *p_invq, *p_kv, *p_sa, *p_swq, *p_swo;
    signed char *p_ahi, *p_alo, *p_wqhi, *p_wqlo, *p_wohi, *p_wolo;
    cudaGetSymbolAddress((void**)&p_qkv, g_qkv);
    cudaGetSymbolAddress((void**)&p_invq, g_invq);
    cudaGetSymbolAddress((void**)&p_kv, g_kv);
    cudaGetSymbolAddress((void**)&p_sa, g_sa);
    cudaGetSymbolAddress((void**)&p_swq, g_swq);
    cudaGetSymbolAddress((void**)&p_swo, g_swo);
    cudaGetSymbolAddress((void**)&p_ahi, g_a_hi);
    cudaGetSymbolAddress((void**)&p_alo, g_a_lo);
    cudaGetSymbolAddress((void**)&p_wqhi, g_wq_hi);
    cudaGetSymbolAddress((void**)&p_wqlo, g_wq_lo);
    cudaGetSymbolAddress((void**)&p_wohi, g_wo_hi);
    cudaGetSymbolAddress((void**)&p_wolo, g_wo_lo);

    cudaFuncSetAttribute(gemm_i8_kernel,
                         cudaFuncAttributeMaxDynamicSharedMemorySize, GS_TOTAL);

    // Launch order keeps GEMM1 at ncu capture slot #4 (-s 5 -c 1).
    zero_kv_kernel<<<(BB_ * DD_ + 255) / 256, 256>>>(p_kv);
    quant_rows_kernel<<<MM_ / 2, 256>>>(x, p_ahi, p_alo, p_sa);
    quant_rows_kernel<<<E3_ / 2, 256>>>(Wqkv, p_wqhi, p_wqlo, p_swq);
    // 4: GEMM1: qkv = x @ W_qkv^T + b_qkv   (16384 x 3072)
    gemm_i8_kernel<<<dim3(E3_ / 128, MM_ / 128), NTHR, GS_TOTAL>>>(
        p_ahi, p_alo, p_sa, p_wqhi, p_wqlo, p_swq, bqkv, p_qkv, E3_);
    quant_rows_kernel<<<DD_ / 2, 256>>>(Wout, p_wohi, p_wolo, p_swo);
    detect_mask_kernel<<<1, 512>>>(mask);
    stage2_kernel<<<MM_ / 32, 256>>>(p_qkv, mask, p_invq, p_kv);
    // A2 slices overwrite x slices + scales (x no longer needed)
    stage3_quant_kernel<<<MM_, 128>>>(p_qkv, p_invq, p_kv, p_ahi, p_alo, p_sa);
    // GEMM2: out = A2 @ W_out^T + b_out   (16384 x 1024)
    gemm_i8_kernel<<<dim3(DD_ / 128, MM_ / 128), NTHR, GS_TOTAL>>>(
        p_ahi, p_alo, p_sa, p_wohi, p_wolo, p_swo, bout, out, DD_);
}

// round 7
// speedup vs baseline: 6.2246x; 6.2246x over previous
#include <cuda_runtime.h>
#include <cuda_fp16.h>
#include <cstdint>
#include <cstddef>

// ---------------------------------------------------------------------------
// Problem constants
// ---------------------------------------------------------------------------
#define BB_ 4
#define TT_ 4096
#define DD_ 1024
#define MM_ (BB_ * TT_)   // 16384 rows
#define E3_ (3 * DD_)     // 3072

// ---------------------------------------------------------------------------
// Scratch (static device globals -- allocation-free rule)
// ---------------------------------------------------------------------------
__device__ float g_qkv[(size_t)MM_ * E3_];
__device__ __half g_xh[(size_t)MM_ * DD_];     // x fp16, reused as A2 fp16
__device__ __half g_wqh[(size_t)E3_ * DD_];
__device__ __half g_woh[(size_t)DD_ * DD_];
__device__ float g_invq[MM_];
__device__ float g_kv[BB_ * DD_];
__device__ int   g_mask_is_byte;

// ---------------------------------------------------------------------------
// Helpers (sm_103 baseline ISA: cp.async, ldmatrix, mma.sync)
// ---------------------------------------------------------------------------
__device__ __forceinline__ uint32_t smem_to_u32(const void* smem_ptr) {
    uint32_t addr;
    asm("{ .reg .u64 tmp; cvta.to.shared.u64 tmp, %1; cvt.u32.u64 %0, tmp; }"
        : "=r"(addr) : "l"(smem_ptr));
    return addr;
}

__device__ __forceinline__ void cp16(uint32_t smem_dst, const void* gmem_src) {
    asm volatile("cp.async.cg.shared.global [%0], [%1], 16;\n"
                 :: "r"(smem_dst), "l"(gmem_src));
}
#define CP_ASYNC_COMMIT() asm volatile("cp.async.commit_group;\n" ::: "memory")
#define CP_ASYNC_WAIT_1() asm volatile("cp.async.wait_group 1;\n" ::: "memory")
#define CP_ASYNC_WAIT_0() asm volatile("cp.async.wait_group 0;\n" ::: "memory")

#define LDSM_X4(r0, r1, r2, r3, addr) \
    asm volatile("ldmatrix.sync.aligned.m8n8.x4.shared.b16 {%0,%1,%2,%3}, [%4];" \
                 : "=r"(r0), "=r"(r1), "=r"(r2), "=r"(r3) : "r"(addr))

// fp16 MMA with fp32 accumulate
#define MMA_16816_F16(c, a, b) \
    asm volatile("mma.sync.aligned.m16n8k16.row.col.f32.f16.f16.f32 " \
                 "{%0,%1,%2,%3}, {%4,%5,%6,%7}, {%8,%9}, {%0,%1,%2,%3};" \
                 : "+f"((c)[0]), "+f"((c)[1]), "+f"((c)[2]), "+f"((c)[3]) \
                 : "r"((a)[0]), "r"((a)[1]), "r"((a)[2]), "r"((a)[3]), \
                   "r"((b)[0]), "r"((b)[1]))

#define SMEM_SWIZZLE_128B(byte_offset) \
    ((byte_offset) ^ (((byte_offset) >> 3) & 0x70))

// ---------------------------------------------------------------------------
// fp16 GEMM: C[M,N] = A @ B^T + bias      (A:(M,1024) B:(N,1024) fp16 rowmaj)
// CTA tile 128(M) x 256(N), BK=64; 512 thr = 16 warps 4(M)x4(N), warp 32x64.
// Stage: [A 16KB][B 32KB] = 48KB; 3-stage cp.async ring (144KB).
// ---------------------------------------------------------------------------
#define STAGES 3
#define STAGE_BYTES 49152
#define GS_TOTAL (STAGES * STAGE_BYTES)   // 147456
#define NKT 16                            // 1024 / 64
#define NTHR 512

__device__ __forceinline__ void gemm_issue_load(
    uint32_t sb, int slot, int tid, int m0, int n0, int k0,
    const __half* __restrict__ A, const __half* __restrict__ B)
{
    uint32_t base = sb + slot * STAGE_BYTES;
    #pragma unroll
    for (int i = 0; i < 2; i++) {           // A: 128 rows x 8 chunks = 1024
        int id = tid + (i << 9);
        int r  = id >> 3;
        int cc = id & 7;
        uint32_t soff = SMEM_SWIZZLE_128B((uint32_t)((r << 7) + (cc << 4)));
        cp16(base + soff, A + (size_t)(m0 + r) * DD_ + k0 + (cc << 3));
    }
    #pragma unroll
    for (int i = 0; i < 4; i++) {           // B: 256 rows x 8 chunks = 2048
        int id = tid + (i << 9);
        int r  = id >> 3;
        int cc = id & 7;
        uint32_t soff = SMEM_SWIZZLE_128B((uint32_t)((r << 7) + (cc << 4)));
        cp16(base + 16384 + soff, B + (size_t)(n0 + r) * DD_ + k0 + (cc << 3));
    }
    CP_ASYNC_COMMIT();
}

__global__ __launch_bounds__(NTHR, 1) void gemm_f16_kernel(
    const __half* __restrict__ A, const __half* __restrict__ B,
    const float* __restrict__ bias, float* __restrict__ C, int N)
{
    extern __shared__ char smem[];
    uint32_t sb = smem_to_u32(smem);
    const int tid = threadIdx.x;
    const int wid = tid >> 5;
    const int lane = tid & 31;
    const int n0 = blockIdx.x * 256;   // N fast-varying: wave shares A via L2
    const int m0 = blockIdx.y * 128;
    const int warp_m = (wid & 3) * 32;     // 4 M-groups of 32
    const int warp_n = (wid >> 2) * 64;    // 4 N-groups of 64

    // ldmatrix per-lane address components (validated R2-R5)
    const int lr = lane & 7;
    const int a_row = warp_m + lr + ((lane & 8) ? 8 : 0);
    const int a_ksel = (lane & 16) ? 16 : 0;
    const int b_row = warp_n + lr + ((lane & 16) ? 8 : 0);
    const int b_ksel = (lane & 8) ? 16 : 0;

    float acc[2][8][4];
    #pragma unroll
    for (int i = 0; i < 2; i++)
        #pragma unroll
        for (int j = 0; j < 8; j++)
            #pragma unroll
            for (int k = 0; k < 4; k++) acc[i][j][k] = 0.0f;

    // prologue: stages 0,1
    gemm_issue_load(sb, 0, tid, m0, n0, 0,  A, B);
    gemm_issue_load(sb, 1, tid, m0, n0, 64, A, B);

    int slot = 0;
    for (int it = 0; it < NKT; it++) {
        if (it == NKT - 1) { CP_ASYNC_WAIT_0(); } else { CP_ASYNC_WAIT_1(); }
        __syncthreads();

        int nt = it + 2;
        if (nt < NKT) {
            int ns = slot + 2; if (ns >= STAGES) ns -= STAGES;
            gemm_issue_load(sb, ns, tid, m0, n0, nt << 6, A, B);
        }

        uint32_t ab = sb + slot * STAGE_BYTES;
        uint32_t bb = ab + 16384;

        #pragma unroll
        for (int ks = 0; ks < 4; ks++) {
            // B fragments: 64 columns = 4 LDSM_X4 (8 n8 tiles)
            uint32_t bfr[8][2];
            #pragma unroll
            for (int nb = 0; nb < 4; nb++) {
                int row = b_row + nb * 16;
                uint32_t addr = bb + (uint32_t)(row << 7)
                              + (uint32_t)(((ks << 5) + b_ksel) ^ ((row & 7) << 4));
                LDSM_X4(bfr[2 * nb][0], bfr[2 * nb][1],
                        bfr[2 * nb + 1][0], bfr[2 * nb + 1][1], addr);
            }
            // A fragments: 32 rows = 2 LDSM_X4
            uint32_t afr[2][4];
            #pragma unroll
            for (int mf = 0; mf < 2; mf++) {
                int row = a_row + mf * 16;
                uint32_t addr = ab + (uint32_t)(row << 7)
                              + (uint32_t)(((ks << 5) + a_ksel) ^ ((row & 7) << 4));
                LDSM_X4(afr[mf][0], afr[mf][1], afr[mf][2], afr[mf][3], addr);
            }
            #pragma unroll
            for (int mf = 0; mf < 2; mf++)
                #pragma unroll
                for (int nf = 0; nf < 8; nf++)
                    MMA_16816_F16(acc[mf][nf], afr[mf], bfr[nf]);
        }
        slot++; if (slot >= STAGES) slot = 0;
    }

    // epilogue: regs -> gmem with bias
    const int gid = lane >> 2;
    const int t4 = lane & 3;
    #pragma unroll
    for (int mf = 0; mf < 2; mf++) {
        int r0 = m0 + warp_m + mf * 16 + gid;
        #pragma unroll
        for (int nf = 0; nf < 8; nf++) {
            int c = n0 + warp_n + nf * 8 + t4 * 2;
            float2 b2 = *(const float2*)(bias + c);
            float2 v0 = make_float2(acc[mf][nf][0] + b2.x, acc[mf][nf][1] + b2.y);
            float2 v1 = make_float2(acc[mf][nf][2] + b2.x, acc[mf][nf][3] + b2.y);
            *(float2*)(C + (size_t)r0 * N + c) = v0;
            *(float2*)(C + (size_t)(r0 + 8) * N + c) = v1;
        }
    }
}

// ---------------------------------------------------------------------------
// Elementwise / reduction kernels
// ---------------------------------------------------------------------------

// fp32 -> fp16 convert, 8 elems/thread
__global__ void cvt_f16_kernel(const float* __restrict__ in,
                               __half* __restrict__ out, int n8)
{
    int idx = blockIdx.x * blockDim.x + threadIdx.x;
    if (idx >= n8) return;
    float4 a = ((const float4*)in)[idx * 2];
    float4 b = ((const float4*)in)[idx * 2 + 1];
    union { uint4 u; __half2 h[4]; } r;
    r.h[0] = __floats2half2_rn(a.x, a.y);
    r.h[1] = __floats2half2_rn(a.z, a.w);
    r.h[2] = __floats2half2_rn(b.x, b.y);
    r.h[3] = __floats2half2_rn(b.z, b.w);
    ((uint4*)out)[idx] = r.u;
}

__global__ void zero_kv_kernel(float* __restrict__ kv)
{
    int i = blockIdx.x * blockDim.x + threadIdx.x;
    if (i < BB_ * DD_) kv[i] = 0.0f;
}

__global__ void detect_mask_kernel(const unsigned char* __restrict__ m)
{
    __shared__ int any;
    if (threadIdx.x == 0) any = 0;
    __syncthreads();
    int acc = 0;
    for (int i = threadIdx.x; i < MM_; i += blockDim.x)
        if ((i & 3) != 0) acc |= m[i];
    if (acc) atomicOr(&any, 1);
    __syncthreads();
    if (threadIdx.x == 0) g_mask_is_byte = any ? 1 : 0;
}

__global__ __launch_bounds__(256) void stage2_kernel(
    const float* __restrict__ qkv, const unsigned char* __restrict__ mask,
    float* __restrict__ invq, float* __restrict__ kv)
{
    __shared__ float s_ik[32];
    int tid = threadIdx.x, lane = tid & 31, warp = tid >> 5;
    int R0 = blockIdx.x * 32;
    int b = R0 >> 12;
    int maskIsByte = g_mask_is_byte;
    const int* mask32 = (const int*)mask;

    #pragma unroll
    for (int rr = 0; rr < 4; rr++) {
        int row = R0 + warp * 4 + rr;
        const float4* base = (const float4*)(qkv + (size_t)row * E3_);
        float sq = 0.f, sk = 0.f;
        #pragma unroll
        for (int j = 0; j < 8; j++) {
            float4 q4 = base[lane + 32 * j];
            float4 k4 = base[256 + lane + 32 * j];
            sq += q4.x*q4.x + q4.y*q4.y + q4.z*q4.z + q4.w*q4.w;
            sk += k4.x*k4.x + k4.y*k4.y + k4.z*k4.z + k4.w*k4.w;
        }
        #pragma unroll
        for (int o = 16; o > 0; o >>= 1) {
            sq += __shfl_xor_sync(0xffffffffu, sq, o);
            sk += __shfl_xor_sync(0xffffffffu, sk, o);
        }
        if (lane == 0) {
            invq[row] = rsqrtf(sq);
            s_ik[warp * 4 + rr] = rsqrtf(sk);
        }
    }
    __syncthreads();

    float ax = 0.f, ay = 0.f, az = 0.f, aw = 0.f;
    for (int r = 0; r < 32; r++) {
        int row = R0 + r;
        bool msk = maskIsByte ? (mask[row] != 0) : (mask32[row] != 0);
        if (!msk) {
            float ik = s_ik[r];
            const float4* base = (const float4*)(qkv + (size_t)row * E3_);
            float4 k4 = base[256 + tid];
            float4 v4 = base[512 + tid];
            ax += k4.x * ik * v4.x;
            ay += k4.y * ik * v4.y;
            az += k4.z * ik * v4.z;
            aw += k4.w * ik * v4.w;
        }
    }
    float* kvb = kv + b * DD_ + tid * 4;
    atomicAdd(kvb + 0, ax);
    atomicAdd(kvb + 1, ay);
    atomicAdd(kvb + 2, az);
    atomicAdd(kvb + 3, aw);
}

// A2 = q * invq[row] * kv[b,:] -> fp16. One 128-thread block per row.
__global__ __launch_bounds__(128) void stage3_kernel(
    const float* __restrict__ qkv, const float* __restrict__ invq,
    const float* __restrict__ kv, __half* __restrict__ out)
{
    int tid = threadIdx.x;
    int row = blockIdx.x;
    int b = row >> 12;
    float s = invq[row];
    const float* qp = qkv + (size_t)row * E3_ + tid * 8;
    const float* kp = kv + b * DD_ + tid * 8;
    float4 q0 = *(const float4*)(qp);
    float4 q1 = *(const float4*)(qp + 4);
    float4 k0 = *(const float4*)(kp);
    float4 k1 = *(const float4*)(kp + 4);
    union { uint4 u; __half2 h[4]; } r;
    r.h[0] = __floats2half2_rn(q0.x * s * k0.x, q0.y * s * k0.y);
    r.h[1] = __floats2half2_rn(q0.z * s * k0.z, q0.w * s * k0.w);
    r.h[2] = __floats2half2_rn(q1.x * s * k1.x, q1.y * s * k1.y);
    r.h[3] = __floats2half2_rn(q1.z * s * k1.z, q1.w * s * k1.w);
    *(uint4*)(out + (size_t)row * DD_ + tid * 8) = r.u;
}

// ---------------------------------------------------------------------------
// Launch
// ---------------------------------------------------------------------------
extern "C" void kernel_launch(void* const* d_in, const int* in_sizes, int n_in,
                              void* d_out, int out_size)
{
    const float* x = (const float*)d_in[0];
    const unsigned char* mask = (const unsigned char*)d_in[1];
    const float* Wqkv = (const float*)d_in[2];
    const float* bqkv = (const float*)d_in[3];
    const float* Wout = (const float*)d_in[4];
    const float* bout = (const float*)d_in[5];
    float* out = (float*)d_out;

    float *p_qkv, *p_invq, *p_kv;
    __half *p_xh, *p_wqh, *p_woh;
    cudaGetSymbolAddress((void**)&p_qkv, g_qkv);
    cudaGetSymbolAddress((void**)&p_invq, g_invq);
    cudaGetSymbolAddress((void**)&p_kv, g_kv);
    cudaGetSymbolAddress((void**)&p_xh, g_xh);
    cudaGetSymbolAddress((void**)&p_wqh, g_wqh);
    cudaGetSymbolAddress((void**)&p_woh, g_woh);

    cudaFuncSetAttribute(gemm_f16_kernel,
                         cudaFuncAttributeMaxDynamicSharedMemorySize, GS_TOTAL);

    // Launch order keeps GEMM1 at ncu capture slot #4 (-s 5 -c 1).
    zero_kv_kernel<<<(BB_ * DD_ + 255) / 256, 256>>>(p_kv);
    cvt_f16_kernel<<<(MM_ * DD_ / 8 + 255) / 256, 256>>>(x, p_xh, MM_ * DD_ / 8);
    cvt_f16_kernel<<<(E3_ * DD_ / 8 + 255) / 256, 256>>>(Wqkv, p_wqh, E3_ * DD_ / 8);
    // 4: GEMM1: qkv = x @ W_qkv^T + b_qkv   (16384 x 3072)
    gemm_f16_kernel<<<dim3(E3_ / 256, MM_ / 128), NTHR, GS_TOTAL>>>(
        p_xh, p_wqh, bqkv, p_qkv, E3_);
    cvt_f16_kernel<<<(DD_ * DD_ / 8 + 255) / 256, 256>>>(Wout, p_woh, DD_ * DD_ / 8);
    detect_mask_kernel<<<1, 512>>>(mask);
    stage2_kernel<<<MM_ / 32, 256>>>(p_qkv, mask, p_invq, p_kv);
    // A2 fp16 overwrites x fp16 buffer
    stage3_kernel<<<MM_, 128>>>(p_qkv, p_invq, p_kv, p_xh);
    // GEMM2: out = A2 @ W_out^T + b_out   (16384 x 1024)
    gemm_f16_kernel<<<dim3(DD_ / 256, MM_ / 128), NTHR, GS_TOTAL>>>(
        p_xh, p_woh, bout, out, DD_);
}